// round 7
// baseline (speedup 1.0000x reference)
#include <cuda_runtime.h>

// Shapes (this instance): B=2048, L=196, M=16, NBL=10. Derived from in_sizes.
#define MAXSITES 256
#define ROW_B   176                 // padded smem row: 128B data + 48B pad
#define TILE_B  (16 * ROW_B)        // 2816 B per site tile
#define RING_B  (3 * 4 * TILE_B)    // 3 slots x (2 dirs x 2 sites) = 33792 B

typedef unsigned long long ull;

// Packed row-form tensors, 16B chunks contiguous (padding added at cp.async):
//  PKL[s][r][j] = {A0[2j][r], A0[2j+1][r], A1[2j][r], A1[2j+1][r]}   (A^T rows)
//  PKR[s'][r][j]= {A0[r][2j], A0[r][2j+1], A1[r][2j], A1[r][2j+1]}, s' reversed
__device__ float4 g_PKL[MAXSITES * 128];
__device__ float4 g_PKR[MAXSITES * 128];
__device__ unsigned g_count = 0;
__device__ volatile unsigned g_gen = 0;

// ---------------------------------------------------------------------------
__device__ __forceinline__ void fma2(ull& d, ull a, ull b) {
    asm("fma.rn.f32x2 %0, %1, %2, %0;" : "+l"(d) : "l"(a), "l"(b));
}
__device__ __forceinline__ float hsum2(ull v) {
    float x, y; asm("mov.b64 {%0,%1}, %2;" : "=f"(x), "=f"(y) : "l"(v));
    return x + y;
}
__device__ __forceinline__ void cpasync16(unsigned dst, const void* src) {
    asm volatile("cp.async.cg.shared.global [%0], [%1], 16;\n"
                 :: "r"(dst), "l"(src) : "memory");
}
__device__ __forceinline__ void cpcommit() {
    asm volatile("cp.async.commit_group;\n" ::: "memory");
}
template<int N> __device__ __forceinline__ void cpwait() {
    asm volatile("cp.async.wait_group %0;\n" :: "n"(N) : "memory");
}

// ---------------------------------------------------------------------------
// Megakernel: prep -> grid barrier -> chains -> fused combine.
// Block = 256 thr = 16 samples: warps 0-3 run LEFT chains, 4-7 RIGHT chains
// of the same 16 samples; combine happens in-block.
// ---------------------------------------------------------------------------
__global__ void __launch_bounds__(256, 1)
mega_kernel(const float* __restrict__ inputs,
            const float* __restrict__ A_left,
            const float* __restrict__ A_mid,
            const float* __restrict__ A_right,
            const float* __restrict__ T,
            const int*   __restrict__ pos_ptr,
            float* __restrict__ out,
            int B, int L, int NBL, int nblocks) {
    extern __shared__ __align__(16) char smem[];
    const int Lm2 = L - 2;
    float4* ring = (float4*)smem;                               // RING_B
    float2* sX   = (float2*)(smem + RING_B);                    // 16*L*8
    float*  sV   = (float*)(smem + RING_B + 16 * L * 8);        // 2*32*24 fl
    float*  sLR  = (float*)(smem + RING_B + 16 * L * 8 + 6144); // 512 fl

    int tid  = threadIdx.x;
    int w    = tid >> 5;
    int lane = tid & 31;
    int q    = lane & 7;
    int ch   = lane >> 3;

    // ---- stage sX: each warp copies 2 sample rows (coalesced) --------------
    {
        const float2* in2 = (const float2*)inputs;
        int s0 = blockIdx.x * 16;
#pragma unroll
        for (int k = 0; k < 2; ++k) {
            int sm = w * 2 + k;
            const float2* src = in2 + (s0 + sm) * L;
            for (int i = lane; i < L; i += 32) sX[sm * L + i] = __ldg(src + i);
        }
    }

    // ---- prep: pack A_mid into PKL (transposed rows) + PKR (reversed) ------
    {
        float* sraw = (float*)ring;                 // 512 floats scratch
        for (int s = blockIdx.x; s < Lm2; s += nblocks) {
            __syncthreads();
            if (tid < 128)
                ((float4*)sraw)[tid] = __ldg((const float4*)(A_mid + s * 512) + tid);
            __syncthreads();
            int idx = tid & 127;
            int r = idx >> 3, j = idx & 7;
            if (tid < 128) {
                float4 o;
                o.x = sraw[(2 * j) * 16 + r];
                o.y = sraw[(2 * j + 1) * 16 + r];
                o.z = sraw[256 + (2 * j) * 16 + r];
                o.w = sraw[256 + (2 * j + 1) * 16 + r];
                g_PKL[s * 128 + idx] = o;
            } else {
                float4 o;
                o.x = sraw[r * 16 + 2 * j];
                o.y = sraw[r * 16 + 2 * j + 1];
                o.z = sraw[256 + r * 16 + 2 * j];
                o.w = sraw[256 + r * 16 + 2 * j + 1];
                g_PKR[(Lm2 - 1 - s) * 128 + idx] = o;
            }
        }
    }

    // ---- grid barrier (generation-based; grid <= resident capacity) --------
    __threadfence();
    __syncthreads();
    if (tid == 0) {
        unsigned gen = g_gen;
        if (atomicAdd(&g_count, 1) == (unsigned)(nblocks - 1)) {
            g_count = 0;
            __threadfence();
            g_gen = gen + 1;
        } else {
            while (g_gen == gen) __nanosleep(64);
        }
        __threadfence();
    }
    __syncthreads();

    // ---- chain setup --------------------------------------------------------
    int pos = __ldg(pos_ptr);
    bool isLeft = (w < 4);
    int sm   = (isLeft ? w : (w - 4)) * 4 + ch;    // local sample 0..15
    int cidx = (isLeft ? 0 : 16) + sm;             // chain slot 0..31
    int nsL = pos, nsR = Lm2 - pos;
    int nsites = isLeft ? nsL : nsR;
    const float* seedA = isLeft ? A_left : A_right;
    int seedX = isLeft ? 0 : (L - 1);

    float2 xs = sX[sm * L + seedX];
    float v0 = fmaf(xs.y, __ldg(seedA + 16 + q),     xs.x * __ldg(seedA + q));
    float v1 = fmaf(xs.y, __ldg(seedA + 16 + q + 8), xs.x * __ldg(seedA + q + 8));
    {   // seed -> v buffer 0
        float* d = sV + cidx * 24;
        d[q] = v0; d[q + 8] = v1;
    }

    unsigned ringAddr = (unsigned)__cvta_generic_to_shared(ring);

    auto stage_pair = [&](int p, int slot) {
        int s0 = 2 * p;
#pragma unroll
        for (int kk = 0; kk < 2; ++kk) {
            int chunk  = tid + kk * 256;           // 0..511
            int tile   = chunk >> 7;               // 0,1: L | 2,3: R
            int within = chunk & 127;
            int site   = s0 + (tile & 1);
            bool isR   = (tile >> 1) != 0;
            if (site < (isR ? nsR : nsL)) {
                const float4* src = (isR ? g_PKR : g_PKL) + site * 128 + within;
                int row = within >> 3, j = within & 7;
                unsigned dst = ringAddr + slot * (4 * TILE_B) + tile * TILE_B
                             + row * ROW_B + j * 16;
                cpasync16(dst, src);
            }
        }
        cpcommit();
    };

    auto do_site = [&](int s, int slot) {
        if (s >= nsites) return;
        const char* tile = (const char*)ring + slot * (4 * TILE_B)
                         + (isLeft ? 0 : 2 * TILE_B) + (s & 1) * TILE_B;
        int vb = s & 1;
        const ulonglong2* vp4 = (const ulonglong2*)(sV + vb * 768 + cidx * 24);
        ull vp[8];
#pragma unroll
        for (int j2 = 0; j2 < 4; ++j2) {
            ulonglong2 t2 = vp4[j2];
            vp[2 * j2] = t2.x; vp[2 * j2 + 1] = t2.y;
        }
        float2 x = sX[sm * L + (isLeft ? (1 + s) : (L - 2 - s))];
        const char* rowq  = tile + q * ROW_B;
        const char* rowq8 = tile + (q + 8) * ROW_B;
        ull a0 = 0ull, a1 = 0ull, b0 = 0ull, b1 = 0ull;
#pragma unroll
        for (int j = 0; j < 8; ++j) {
            ulonglong2 mq  = *(const ulonglong2*)(rowq  + j * 16);
            ulonglong2 mq8 = *(const ulonglong2*)(rowq8 + j * 16);
            fma2(a0, vp[j], mq.x);
            fma2(a1, vp[j], mq.y);
            fma2(b0, vp[j], mq8.x);
            fma2(b1, vp[j], mq8.y);
        }
        v0 = fmaf(x.y, hsum2(a1), x.x * hsum2(a0));
        v1 = fmaf(x.y, hsum2(b1), x.x * hsum2(b0));
        float* d = sV + (1 - vb) * 768 + cidx * 24;
        d[q] = v0; d[q + 8] = v1;
    };

    // ---- main loop: 2 sites per barrier, 3-slot cp.async ring ---------------
    int maxs = nsL > nsR ? nsL : nsR;
    int P = (maxs + 1) >> 1;
    if (P > 0) stage_pair(0, 0); else cpcommit();
    if (P > 1) stage_pair(1, 1); else cpcommit();
    for (int t = 0; t < P; ++t) {
        cpwait<1>();
        __syncthreads();
        if (t + 2 < P) stage_pair(t + 2, (t + 2) % 3); else cpcommit();
        do_site(2 * t,     t % 3);
        do_site(2 * t + 1, t % 3);
    }
    cpwait<0>();

    // ---- publish chain results, fused combine -------------------------------
    float* sL = sLR;
    float* sR = sLR + 256;
    {
        float* d = (isLeft ? sL : sR) + sm * 16;
        d[q] = v0; d[q + 8] = v1;
    }
    __syncthreads();

    float* sT = (float*)ring;                       // reuse ring for T
    int tElems = 256 * NBL;
    for (int i = tid; i < tElems; i += 256) sT[i] = __ldg(T + i);
    __syncthreads();

    int total = 16 * NBL;
    if (tid < total) {
        int b = tid / NBL, l = tid - b * NBL;
        float acc = 0.f;
#pragma unroll
        for (int m = 0; m < 16; ++m) {
            float t2 = 0.f;
#pragma unroll
            for (int k = 0; k < 16; ++k)
                t2 = fmaf(sT[(m * 16 + k) * NBL + l], sR[b * 16 + k], t2);
            acc = fmaf(sL[b * 16 + m], t2, acc);
        }
        out[(blockIdx.x * 16 + b) * NBL + l] = acc;
    }
}

// ---------------------------------------------------------------------------
extern "C" void kernel_launch(void* const* d_in, const int* in_sizes, int n_in,
                              void* d_out, int out_size) {
    const float* inputs  = (const float*)d_in[0];
    const float* A_left  = (const float*)d_in[1];
    const float* A_mid   = (const float*)d_in[2];
    const float* A_right = (const float*)d_in[3];
    const float* T_out   = (const float*)d_in[4];
    const int*   pos     = (const int*)d_in[5];

    int Lm2 = in_sizes[2] / 512;          // L-2 = 194
    int L   = Lm2 + 2;                    // 196
    int B   = in_sizes[0] / (2 * L);      // 2048
    int NBL = in_sizes[4] / 256;          // 10

    int nblocks = B / 16;                 // 128
    size_t smemB = (size_t)RING_B + (size_t)16 * L * 8 + 6144 + 2048;

    cudaFuncSetAttribute(mega_kernel,
                         cudaFuncAttributeMaxDynamicSharedMemorySize,
                         (int)smemB);

    mega_kernel<<<nblocks, 256, smemB>>>(inputs, A_left, A_mid, A_right,
                                         T_out, pos, (float*)d_out,
                                         B, L, NBL, nblocks);
}

// round 8
// speedup vs baseline: 1.0423x; 1.0423x over previous
#include <cuda_runtime.h>

// Shapes (this instance): B=2048, L=196, M=16, NBL=10. Derived from in_sizes.
#define MAXSITES 256
#define ROW_B   176                 // padded smem row: 128B data + 48B pad
#define TILE_B  (16 * ROW_B)        // 2816 B per site tile
#define RING_B  (3 * 4 * TILE_B)    // 3 slots x (2 dirs x 2 sites) = 33792 B
#define SV_B    3072                // 2 bufs x 16 chains x 24 floats
#define SLR_B   1024                // 2 x 8 samples x 16 floats

typedef unsigned long long ull;

// Packed row-form tensors, 16B chunks contiguous (padding added at cp.async):
//  PKL[s][r][j] = {A0[2j][r], A0[2j+1][r], A1[2j][r], A1[2j+1][r]}   (A^T rows)
//  PKR[s'][r][j]= {A0[r][2j], A0[r][2j+1], A1[r][2j], A1[r][2j+1]}, s' reversed
__device__ float4 g_PKL[MAXSITES * 128];
__device__ float4 g_PKR[MAXSITES * 128];
__device__ unsigned g_count = 0;
__device__ volatile unsigned g_gen = 0;

// ---------------------------------------------------------------------------
__device__ __forceinline__ void fma2(ull& d, ull a, ull b) {
    asm("fma.rn.f32x2 %0, %1, %2, %0;" : "+l"(d) : "l"(a), "l"(b));
}
__device__ __forceinline__ float hsum2(ull v) {
    float x, y; asm("mov.b64 {%0,%1}, %2;" : "=f"(x), "=f"(y) : "l"(v));
    return x + y;
}
__device__ __forceinline__ void cpasync16(unsigned dst, const void* src) {
    asm volatile("cp.async.cg.shared.global [%0], [%1], 16;\n"
                 :: "r"(dst), "l"(src) : "memory");
}
__device__ __forceinline__ void cpcommit() {
    asm volatile("cp.async.commit_group;\n" ::: "memory");
}
template<int N> __device__ __forceinline__ void cpwait() {
    asm volatile("cp.async.wait_group %0;\n" :: "n"(N) : "memory");
}

// ---------------------------------------------------------------------------
// Megakernel: prep -> grid barrier -> chains -> fused combine.
// Block = 128 thr = 8 samples: warps 0-1 run LEFT chains, 2-3 RIGHT chains
// of the same 8 samples; combine happens in-block. 256 blocks -> 2 per SM,
// so one block's barriers are covered by the other block's issue.
// ---------------------------------------------------------------------------
__global__ void __launch_bounds__(128, 2)
mega_kernel(const float* __restrict__ inputs,
            const float* __restrict__ A_left,
            const float* __restrict__ A_mid,
            const float* __restrict__ A_right,
            const float* __restrict__ T,
            const int*   __restrict__ pos_ptr,
            float* __restrict__ out,
            int B, int L, int NBL, int nblocks) {
    extern __shared__ __align__(16) char smem[];
    const int Lm2 = L - 2;
    float4* ring = (float4*)smem;                        // RING_B
    float*  sV   = (float*)(smem + RING_B);              // SV_B
    float*  sLR  = (float*)(smem + RING_B + SV_B);       // SLR_B

    int tid  = threadIdx.x;
    int w    = tid >> 5;
    int lane = tid & 31;
    int q    = lane & 7;
    int ch   = lane >> 3;

    const float2* in2 = (const float2*)inputs;           // (B,L) float2

    // ---- prep: pack A_mid into PKL (transposed rows) + PKR (reversed) ------
    {
        float* sraw = (float*)ring;                      // 512 floats scratch
        for (int s = blockIdx.x; s < Lm2; s += nblocks) {
            __syncthreads();
            ((float4*)sraw)[tid] = __ldg((const float4*)(A_mid + s * 512) + tid);
            __syncthreads();
            int r = tid >> 3, j = tid & 7;               // tid = 0..127
            float4 oL, oR;
            oL.x = sraw[(2 * j) * 16 + r];
            oL.y = sraw[(2 * j + 1) * 16 + r];
            oL.z = sraw[256 + (2 * j) * 16 + r];
            oL.w = sraw[256 + (2 * j + 1) * 16 + r];
            oR.x = sraw[r * 16 + 2 * j];
            oR.y = sraw[r * 16 + 2 * j + 1];
            oR.z = sraw[256 + r * 16 + 2 * j];
            oR.w = sraw[256 + r * 16 + 2 * j + 1];
            g_PKL[s * 128 + tid] = oL;
            g_PKR[(Lm2 - 1 - s) * 128 + tid] = oR;
        }
    }

    // ---- grid barrier (generation-based; 256 blocks all co-resident) -------
    __threadfence();
    __syncthreads();
    if (tid == 0) {
        unsigned gen = g_gen;
        if (atomicAdd(&g_count, 1) == (unsigned)(nblocks - 1)) {
            g_count = 0;
            __threadfence();
            g_gen = gen + 1;
        } else {
            while (g_gen == gen) __nanosleep(64);
        }
        __threadfence();
    }
    __syncthreads();

    // ---- chain setup --------------------------------------------------------
    int pos = __ldg(pos_ptr);
    bool isLeft = (w < 2);
    int sm   = (isLeft ? w : (w - 2)) * 4 + ch;    // local sample 0..7
    int cidx = (isLeft ? 0 : 8) + sm;              // chain slot 0..15
    int c    = blockIdx.x * 8 + sm;                // global sample
    int nsL = pos, nsR = Lm2 - pos;
    int nsites = isLeft ? nsL : nsR;
    const float* seedA = isLeft ? A_left : A_right;
    int seedX = isLeft ? 0 : (L - 1);

    float2 xs = __ldg(in2 + c * L + seedX);
    float v0 = fmaf(xs.y, __ldg(seedA + 16 + q),     xs.x * __ldg(seedA + q));
    float v1 = fmaf(xs.y, __ldg(seedA + 16 + q + 8), xs.x * __ldg(seedA + q + 8));
    {   // seed -> v buffer 0
        float* d = sV + cidx * 24;
        d[q] = v0; d[q + 8] = v1;
    }

    unsigned ringAddr = (unsigned)__cvta_generic_to_shared(ring);

    auto stage_pair = [&](int p, int slot) {
        int s0 = 2 * p;
#pragma unroll
        for (int kk = 0; kk < 4; ++kk) {
            int chunk  = tid + kk * 128;           // 0..511
            int tile   = chunk >> 7;               // 0,1: L | 2,3: R
            int within = chunk & 127;
            int site   = s0 + (tile & 1);
            bool isR   = (tile >> 1) != 0;
            if (site < (isR ? nsR : nsL)) {
                const float4* src = (isR ? g_PKR : g_PKL) + site * 128 + within;
                int row = within >> 3, j = within & 7;
                unsigned dst = ringAddr + slot * (4 * TILE_B) + tile * TILE_B
                             + row * ROW_B + j * 16;
                cpasync16(dst, src);
            }
        }
        cpcommit();
    };

    auto do_site = [&](int s, int slot) {
        if (s >= nsites) return;
        const char* tile = (const char*)ring + slot * (4 * TILE_B)
                         + (isLeft ? 0 : 2 * TILE_B) + (s & 1) * TILE_B;
        int vb = s & 1;
        const ulonglong2* vp4 = (const ulonglong2*)(sV + vb * 384 + cidx * 24);
        ull vp[8];
#pragma unroll
        for (int j2 = 0; j2 < 4; ++j2) {
            ulonglong2 t2 = vp4[j2];
            vp[2 * j2] = t2.x; vp[2 * j2 + 1] = t2.y;
        }
        float2 x = __ldg(in2 + c * L + (isLeft ? (1 + s) : (L - 2 - s)));
        const char* rowq  = tile + q * ROW_B;
        const char* rowq8 = tile + (q + 8) * ROW_B;
        ull a0 = 0ull, a1 = 0ull, b0 = 0ull, b1 = 0ull;
#pragma unroll
        for (int j = 0; j < 8; ++j) {
            ulonglong2 mq  = *(const ulonglong2*)(rowq  + j * 16);
            ulonglong2 mq8 = *(const ulonglong2*)(rowq8 + j * 16);
            fma2(a0, vp[j], mq.x);
            fma2(a1, vp[j], mq.y);
            fma2(b0, vp[j], mq8.x);
            fma2(b1, vp[j], mq8.y);
        }
        v0 = fmaf(x.y, hsum2(a1), x.x * hsum2(a0));
        v1 = fmaf(x.y, hsum2(b1), x.x * hsum2(b0));
        float* d = sV + (1 - vb) * 384 + cidx * 24;
        d[q] = v0; d[q + 8] = v1;
    };

    // ---- main loop: 2 sites per barrier, 3-slot cp.async ring ---------------
    int maxs = nsL > nsR ? nsL : nsR;
    int P = (maxs + 1) >> 1;
    if (P > 0) stage_pair(0, 0); else cpcommit();
    if (P > 1) stage_pair(1, 1); else cpcommit();
    for (int t = 0; t < P; ++t) {
        cpwait<1>();
        __syncthreads();
        if (t + 2 < P) stage_pair(t + 2, (t + 2) % 3); else cpcommit();
        do_site(2 * t,     t % 3);
        do_site(2 * t + 1, t % 3);
    }
    cpwait<0>();

    // ---- publish chain results, fused combine -------------------------------
    float* sL = sLR;
    float* sR = sLR + 128;
    {
        float* d = (isLeft ? sL : sR) + sm * 16;
        d[q] = v0; d[q + 8] = v1;
    }
    __syncthreads();

    float* sT = (float*)ring;                       // reuse ring for T
    int tElems = 256 * NBL;
    for (int i = tid; i < tElems; i += 128) sT[i] = __ldg(T + i);
    __syncthreads();

    int total = 8 * NBL;
    if (tid < total) {
        int b = tid / NBL, l = tid - b * NBL;
        float acc = 0.f;
#pragma unroll
        for (int m = 0; m < 16; ++m) {
            float t2 = 0.f;
#pragma unroll
            for (int k = 0; k < 16; ++k)
                t2 = fmaf(sT[(m * 16 + k) * NBL + l], sR[b * 16 + k], t2);
            acc = fmaf(sL[b * 16 + m], t2, acc);
        }
        out[(blockIdx.x * 8 + b) * NBL + l] = acc;
    }
}

// ---------------------------------------------------------------------------
extern "C" void kernel_launch(void* const* d_in, const int* in_sizes, int n_in,
                              void* d_out, int out_size) {
    const float* inputs  = (const float*)d_in[0];
    const float* A_left  = (const float*)d_in[1];
    const float* A_mid   = (const float*)d_in[2];
    const float* A_right = (const float*)d_in[3];
    const float* T_out   = (const float*)d_in[4];
    const int*   pos     = (const int*)d_in[5];

    int Lm2 = in_sizes[2] / 512;          // L-2 = 194
    int L   = Lm2 + 2;                    // 196
    int B   = in_sizes[0] / (2 * L);      // 2048
    int NBL = in_sizes[4] / 256;          // 10

    int nblocks = B / 8;                  // 256
    size_t smemB = (size_t)RING_B + SV_B + SLR_B;   // ~37.9 KB

    cudaFuncSetAttribute(mega_kernel,
                         cudaFuncAttributeMaxDynamicSharedMemorySize,
                         (int)smemB);

    mega_kernel<<<nblocks, 128, smemB>>>(inputs, A_left, A_mid, A_right,
                                         T_out, pos, (float*)d_out,
                                         B, L, NBL, nblocks);
}

// round 9
// speedup vs baseline: 1.3099x; 1.2567x over previous
#include <cuda_runtime.h>

// Shapes (this instance): B=2048, L=196, M=16, NBL=10. Derived from in_sizes.
#define MAXSITES 256
#define ROW_B   176                 // padded smem row: 128B data + 48B pad
#define TILE_B  (16 * ROW_B)        // 2816 B per site tile
#define NSLOT   4
#define RING_B  (NSLOT * 4 * TILE_B)  // 4 slots x (2 dirs x 2 sites) = 45056 B
#define SV_B    6144                // 2 bufs x 32 chains x 24 floats
#define SLR_B   2048                // 2 x 16 samples x 16 floats

typedef unsigned long long ull;

// Packed row-form tensors, 16B chunks contiguous (padding added at cp.async):
//  PKL[s][r][j] = {A0[2j][r], A0[2j+1][r], A1[2j][r], A1[2j+1][r]}   (A^T rows)
//  PKR[s'][r][j]= {A0[r][2j], A0[r][2j+1], A1[r][2j], A1[r][2j+1]}, s' reversed
__device__ float4 g_PKL[MAXSITES * 128];
__device__ float4 g_PKR[MAXSITES * 128];
__device__ unsigned g_count = 0;
__device__ volatile unsigned g_gen = 0;

// ---------------------------------------------------------------------------
__device__ __forceinline__ void fma2(ull& d, ull a, ull b) {
    asm("fma.rn.f32x2 %0, %1, %2, %0;" : "+l"(d) : "l"(a), "l"(b));
}
__device__ __forceinline__ float hsum2(ull v) {
    float x, y; asm("mov.b64 {%0,%1}, %2;" : "=f"(x), "=f"(y) : "l"(v));
    return x + y;
}
__device__ __forceinline__ void cpasync16(unsigned dst, const void* src) {
    asm volatile("cp.async.cg.shared.global [%0], [%1], 16;\n"
                 :: "r"(dst), "l"(src) : "memory");
}
__device__ __forceinline__ void cpcommit() {
    asm volatile("cp.async.commit_group;\n" ::: "memory");
}
template<int N> __device__ __forceinline__ void cpwait() {
    asm volatile("cp.async.wait_group %0;\n" :: "n"(N) : "memory");
}

// ---------------------------------------------------------------------------
// Megakernel: prep -> grid barrier -> chains -> fused combine.
// Block = 128 thr = 16 samples. Warps 0-1: LEFT chains, warps 2-3: RIGHT.
// Each lane runs TWO chains (components q,q+8 of samples sm0 and sm0+4), so
// every matrix LDS.128 serves 8 chains per warp. 128 blocks -> 1 per SM.
// ---------------------------------------------------------------------------
__global__ void __launch_bounds__(128, 1)
mega_kernel(const float* __restrict__ inputs,
            const float* __restrict__ A_left,
            const float* __restrict__ A_mid,
            const float* __restrict__ A_right,
            const float* __restrict__ T,
            const int*   __restrict__ pos_ptr,
            float* __restrict__ out,
            int B, int L, int NBL, int nblocks) {
    extern __shared__ __align__(16) char smem[];
    const int Lm2 = L - 2;
    float4* ring = (float4*)smem;                        // RING_B
    float*  sV   = (float*)(smem + RING_B);              // SV_B
    float*  sLR  = (float*)(smem + RING_B + SV_B);       // SLR_B

    int tid  = threadIdx.x;
    int w    = tid >> 5;
    int lane = tid & 31;
    int q    = lane & 7;
    int ch   = lane >> 3;                                // 0..3

    const float2* in2 = (const float2*)inputs;           // (B,L) float2

    // ---- prep: pack A_mid into PKL (transposed rows) + PKR (reversed) ------
    {
        float* sraw = (float*)ring;                      // 512 floats scratch
        for (int s = blockIdx.x; s < Lm2; s += nblocks) {
            __syncthreads();
            ((float4*)sraw)[tid] = __ldg((const float4*)(A_mid + s * 512) + tid);
            __syncthreads();
            int r = tid >> 3, j = tid & 7;               // tid = 0..127
            float4 oL, oR;
            oL.x = sraw[(2 * j) * 16 + r];
            oL.y = sraw[(2 * j + 1) * 16 + r];
            oL.z = sraw[256 + (2 * j) * 16 + r];
            oL.w = sraw[256 + (2 * j + 1) * 16 + r];
            oR.x = sraw[r * 16 + 2 * j];
            oR.y = sraw[r * 16 + 2 * j + 1];
            oR.z = sraw[256 + r * 16 + 2 * j];
            oR.w = sraw[256 + r * 16 + 2 * j + 1];
            g_PKL[s * 128 + tid] = oL;
            g_PKR[(Lm2 - 1 - s) * 128 + tid] = oR;
        }
    }

    // ---- grid barrier (generation-based; 128 blocks all co-resident) -------
    __threadfence();
    __syncthreads();
    if (tid == 0) {
        unsigned gen = g_gen;
        if (atomicAdd(&g_count, 1) == (unsigned)(nblocks - 1)) {
            g_count = 0;
            __threadfence();
            g_gen = gen + 1;
        } else {
            while (g_gen == gen) __nanosleep(64);
        }
        __threadfence();
    }
    __syncthreads();

    // ---- chain setup --------------------------------------------------------
    int pos = __ldg(pos_ptr);
    bool isLeft = (w < 2);
    int wl  = w & 1;
    int sm0 = wl * 8 + ch;                 // first sample of this lane (0..15)
    int sm1 = sm0 + 4;                     // second sample
    int cidx0 = (isLeft ? 0 : 16) + sm0;   // chain slots 0..31
    int cidx1 = (isLeft ? 0 : 16) + sm1;
    int c0 = blockIdx.x * 16 + sm0;        // global samples
    int c1 = blockIdx.x * 16 + sm1;
    int nsL = pos, nsR = Lm2 - pos;
    int nsites = isLeft ? nsL : nsR;
    const float* seedA = isLeft ? A_left : A_right;
    int seedX = isLeft ? 0 : (L - 1);

    float sa0 = __ldg(seedA + q),      sa1 = __ldg(seedA + 16 + q);
    float sb0 = __ldg(seedA + q + 8),  sb1 = __ldg(seedA + 16 + q + 8);
    float2 xsA = __ldg(in2 + c0 * L + seedX);
    float2 xsB = __ldg(in2 + c1 * L + seedX);
    float vA0 = fmaf(xsA.y, sa1, xsA.x * sa0);
    float vA1 = fmaf(xsA.y, sb1, xsA.x * sb0);
    float vB0 = fmaf(xsB.y, sa1, xsB.x * sa0);
    float vB1 = fmaf(xsB.y, sb1, xsB.x * sb0);
    {   // seed -> v buffer 0
        float* dA = sV + cidx0 * 24;
        float* dB = sV + cidx1 * 24;
        dA[q] = vA0; dA[q + 8] = vA1;
        dB[q] = vB0; dB[q + 8] = vB1;
    }

    unsigned ringAddr = (unsigned)__cvta_generic_to_shared(ring);

    auto stage_pair = [&](int p, int slot) {
        int s0 = 2 * p;
#pragma unroll
        for (int kk = 0; kk < 4; ++kk) {
            int chunk  = tid + kk * 128;           // 0..511
            int tile   = chunk >> 7;               // 0,1: L | 2,3: R
            int within = chunk & 127;
            int site   = s0 + (tile & 1);
            bool isR   = (tile >> 1) != 0;
            if (site < (isR ? nsR : nsL)) {
                const float4* src = (isR ? g_PKR : g_PKL) + site * 128 + within;
                int row = within >> 3, j = within & 7;
                unsigned dst = ringAddr + slot * (4 * TILE_B) + tile * TILE_B
                             + row * ROW_B + j * 16;
                cpasync16(dst, src);
            }
        }
        cpcommit();
    };

    auto do_site = [&](int s, int slot) {
        if (s >= nsites) return;
        const char* tile = (const char*)ring + slot * (4 * TILE_B)
                         + (isLeft ? 0 : 2 * TILE_B) + (s & 1) * TILE_B;
        int vb = s & 1;
        ull vpA[8], vpB[8];
        {
            const ulonglong2* pa = (const ulonglong2*)(sV + vb * 768 + cidx0 * 24);
            const ulonglong2* pb = (const ulonglong2*)(sV + vb * 768 + cidx1 * 24);
#pragma unroll
            for (int j2 = 0; j2 < 4; ++j2) {
                ulonglong2 ta = pa[j2], tb = pb[j2];
                vpA[2 * j2] = ta.x; vpA[2 * j2 + 1] = ta.y;
                vpB[2 * j2] = tb.x; vpB[2 * j2 + 1] = tb.y;
            }
        }
        int xsite = isLeft ? (1 + s) : (L - 2 - s);
        float2 xA = __ldg(in2 + c0 * L + xsite);
        float2 xB = __ldg(in2 + c1 * L + xsite);
        const char* rowq  = tile + q * ROW_B;
        const char* rowq8 = tile + (q + 8) * ROW_B;
        ull aA0 = 0ull, aA1 = 0ull, bA0 = 0ull, bA1 = 0ull;   // chain A
        ull aB0 = 0ull, aB1 = 0ull, bB0 = 0ull, bB1 = 0ull;   // chain B
#pragma unroll
        for (int j = 0; j < 8; ++j) {
            ulonglong2 mq  = *(const ulonglong2*)(rowq  + j * 16);
            ulonglong2 mq8 = *(const ulonglong2*)(rowq8 + j * 16);
            fma2(aA0, vpA[j], mq.x);
            fma2(aA1, vpA[j], mq.y);
            fma2(bA0, vpA[j], mq8.x);
            fma2(bA1, vpA[j], mq8.y);
            fma2(aB0, vpB[j], mq.x);
            fma2(aB1, vpB[j], mq.y);
            fma2(bB0, vpB[j], mq8.x);
            fma2(bB1, vpB[j], mq8.y);
        }
        vA0 = fmaf(xA.y, hsum2(aA1), xA.x * hsum2(aA0));
        vA1 = fmaf(xA.y, hsum2(bA1), xA.x * hsum2(bA0));
        vB0 = fmaf(xB.y, hsum2(aB1), xB.x * hsum2(aB0));
        vB1 = fmaf(xB.y, hsum2(bB1), xB.x * hsum2(bB0));
        float* dA = sV + (1 - vb) * 768 + cidx0 * 24;
        float* dB = sV + (1 - vb) * 768 + cidx1 * 24;
        dA[q] = vA0; dA[q + 8] = vA1;
        dB[q] = vB0; dB[q + 8] = vB1;
        __syncwarp();      // publish v(s) before any lane starts site s+1
    };

    // ---- main loop: 2 sites per barrier, 4-slot ring, 2 pairs of slack ------
    int maxs = nsL > nsR ? nsL : nsR;
    int P = (maxs + 1) >> 1;
    if (P > 0) stage_pair(0, 0); else cpcommit();
    if (P > 1) stage_pair(1, 1); else cpcommit();
    if (P > 2) stage_pair(2, 2); else cpcommit();
    for (int t = 0; t < P; ++t) {
        cpwait<2>();            // pair t resident (t+1, t+2 may be in flight)
        __syncthreads();        // all warps past pair t-1; slot (t+3)%4 free
        if (t + 3 < P) stage_pair(t + 3, (t + 3) & 3); else cpcommit();
        do_site(2 * t,     t & 3);
        do_site(2 * t + 1, t & 3);
    }
    cpwait<0>();

    // ---- publish chain results, fused combine -------------------------------
    float* sL = sLR;
    float* sR = sLR + 256;
    {
        float* d = (isLeft ? sL : sR);
        d[sm0 * 16 + q] = vA0; d[sm0 * 16 + q + 8] = vA1;
        d[sm1 * 16 + q] = vB0; d[sm1 * 16 + q + 8] = vB1;
    }
    __syncthreads();

    float* sT = (float*)ring;                       // reuse ring for T
    int tElems = 256 * NBL;
    for (int i = tid; i < tElems; i += 128) sT[i] = __ldg(T + i);
    __syncthreads();

    int total = 16 * NBL;
    for (int i = tid; i < total; i += 128) {
        int b = i / NBL, l = i - b * NBL;
        float acc = 0.f;
#pragma unroll
        for (int m = 0; m < 16; ++m) {
            float t2 = 0.f;
#pragma unroll
            for (int k = 0; k < 16; ++k)
                t2 = fmaf(sT[(m * 16 + k) * NBL + l], sR[b * 16 + k], t2);
            acc = fmaf(sL[b * 16 + m], t2, acc);
        }
        out[(blockIdx.x * 16 + b) * NBL + l] = acc;
    }
}

// ---------------------------------------------------------------------------
extern "C" void kernel_launch(void* const* d_in, const int* in_sizes, int n_in,
                              void* d_out, int out_size) {
    const float* inputs  = (const float*)d_in[0];
    const float* A_left  = (const float*)d_in[1];
    const float* A_mid   = (const float*)d_in[2];
    const float* A_right = (const float*)d_in[3];
    const float* T_out   = (const float*)d_in[4];
    const int*   pos     = (const int*)d_in[5];

    int Lm2 = in_sizes[2] / 512;          // L-2 = 194
    int L   = Lm2 + 2;                    // 196
    int B   = in_sizes[0] / (2 * L);      // 2048
    int NBL = in_sizes[4] / 256;          // 10

    int nblocks = B / 16;                 // 128
    size_t smemB = (size_t)RING_B + SV_B + SLR_B;   // ~52 KB

    cudaFuncSetAttribute(mega_kernel,
                         cudaFuncAttributeMaxDynamicSharedMemorySize,
                         (int)smemB);

    mega_kernel<<<nblocks, 128, smemB>>>(inputs, A_left, A_mid, A_right,
                                         T_out, pos, (float*)d_out,
                                         B, L, NBL, nblocks);
}